// round 1
// baseline (speedup 1.0000x reference)
#include <cuda_runtime.h>
#include <stdint.h>

// Problem constants
#define NROWS  (64*2048)       // 131072 rows
#define DIM    64
#define KC     1024            // number of codes
#define TILE   128             // codes per smem tile
#define BR     128             // rows (threads) per block
#define QELEMS (NROWS*DIM)     // 8388608

// Output layout in d_out (float32):
//   [0]                       loss
//   [1 .. 1+QELEMS)           quantized_st
//   [1+QELEMS .. +NROWS)      encoding indices (as float)

__device__ double g_loss_acc;

static __device__ __forceinline__ unsigned long long pack2(float a, float b){
    unsigned long long r;
    asm("mov.b64 %0, {%1,%2};" : "=l"(r) : "f"(a), "f"(b));
    return r;
}
static __device__ __forceinline__ void unpack2(unsigned long long v, float& a, float& b){
    asm("mov.b64 {%0,%1}, %2;" : "=f"(a), "=f"(b) : "l"(v));
}
static __device__ __forceinline__ unsigned long long ffma2(unsigned long long a,
                                                           unsigned long long b,
                                                           unsigned long long c){
    unsigned long long r;
    asm("fma.rn.f32x2 %0, %1, %2, %3;" : "=l"(r) : "l"(a), "l"(b), "l"(c));
    return r;
}

__global__ void vq_zero_kernel(){ g_loss_acc = 0.0; }

// Kernel A: per-row argmin over 1024 codes + index write + fp64 loss partial.
__global__ __launch_bounds__(BR) void vq_argmin(const float* __restrict__ x,
                                                const float* __restrict__ w,
                                                float* __restrict__ out)
{
    __shared__ __align__(16) float sw[TILE*DIM];   // 32 KB code tile
    __shared__ float  ss[TILE];                    // per-code ||e||^2
    __shared__ double sred[BR/32];

    const int tid = threadIdx.x;
    const int row = blockIdx.x*BR + tid;

    // Load this thread's row into registers.
    float xv[DIM];
    const float4* xr = reinterpret_cast<const float4*>(x + (size_t)row*DIM);
    #pragma unroll
    for (int i=0;i<DIM/4;i++){
        float4 v = xr[i];
        xv[4*i+0]=v.x; xv[4*i+1]=v.y; xv[4*i+2]=v.z; xv[4*i+3]=v.w;
    }
    // ||x||^2 with reference-style rounding: round each product, sequential sum.
    float c = 0.f;
    #pragma unroll
    for (int d=0;d<DIM;d++) c = __fadd_rn(c, __fmul_rn(xv[d],xv[d]));

    // Pack x into f32x2 pairs for packed FMA.
    unsigned long long xp[DIM/2];
    #pragma unroll
    for (int i=0;i<DIM/2;i++) xp[i] = pack2(xv[2*i], xv[2*i+1]);

    unsigned swb = (unsigned)__cvta_generic_to_shared(sw);

    float minv = 3.402823466e38f;
    int   mini = 0;

    for (int t=0;t<KC/TILE;t++){
        // Coalesced tile load: 2048 float4 across 128 threads.
        const float4* wt  = reinterpret_cast<const float4*>(w + (size_t)t*TILE*DIM);
        float4*       swv = reinterpret_cast<float4*>(sw);
        #pragma unroll
        for (int i=0;i<(TILE*DIM/4)/BR;i++)
            swv[tid + i*BR] = wt[tid + i*BR];
        __syncthreads();
        // Per-code squared norms (thread tid handles code tid of the tile).
        {
            float s = 0.f;
            const float* er = sw + tid*DIM;
            #pragma unroll
            for (int d=0;d<DIM;d++) s = __fadd_rn(s, __fmul_rn(er[d],er[d]));
            ss[tid] = s;
        }
        __syncthreads();

        #pragma unroll 1
        for (int cc=0; cc<TILE; cc++){
            unsigned addr = swb + (unsigned)cc*(DIM*4);
            unsigned long long a0=0ull, a1=0ull;
            #pragma unroll
            for (int i=0;i<8;i++){
                unsigned long long e0,e1,e2,e3;
                asm volatile("ld.shared.v2.u64 {%0,%1}, [%2];"
                             : "=l"(e0),"=l"(e1) : "r"(addr + i*32));
                asm volatile("ld.shared.v2.u64 {%0,%1}, [%2];"
                             : "=l"(e2),"=l"(e3) : "r"(addr + i*32 + 16));
                a0 = ffma2(xp[4*i+0], e0, a0);
                a1 = ffma2(xp[4*i+1], e1, a1);
                a0 = ffma2(xp[4*i+2], e2, a0);
                a1 = ffma2(xp[4*i+3], e3, a1);
            }
            float m0,m1,m2,m3;
            unpack2(a0,m0,m1); unpack2(a1,m2,m3);
            float m = __fadd_rn(__fadd_rn(m0,m1), __fadd_rn(m2,m3));
            // dist = (||x||^2 + ||e||^2) - 2*(x.e), matching reference expression.
            float dist = __fsub_rn(__fadd_rn(c, ss[cc]), 2.0f*m);
            if (dist < minv){ minv = dist; mini = t*TILE + cc; }  // first-min semantics
        }
        __syncthreads();
    }

    // Write index (as float).
    out[1 + QELEMS + row] = (float)mini;

    // Loss partial: sum of min distances == sum of ||q - x||^2 per row.
    double v = (double)minv;
    #pragma unroll
    for (int o=16;o>0;o>>=1) v += __shfl_down_sync(0xffffffffu, v, o);
    if ((tid & 31)==0) sred[tid>>5] = v;
    __syncthreads();
    if (tid==0){
        double s=0.0;
        #pragma unroll
        for (int i=0;i<BR/32;i++) s += sred[i];
        atomicAdd(&g_loss_acc, s);
    }
}

// Kernel B: gather quantized vectors + straight-through output (x + (q - x)).
__global__ void vq_gather(const float* __restrict__ x, const float* __restrict__ w,
                          float* __restrict__ out)
{
    int j = blockIdx.x*blockDim.x + threadIdx.x;
    if (j >= QELEMS) return;
    int row = j >> 6;
    int idx = (int)out[1 + QELEMS + row];
    float q  = w[idx*DIM + (j & 63)];
    float xx = x[j];
    out[1 + j] = __fadd_rn(xx, __fsub_rn(q, xx));
}

// Kernel C: finalize loss = q_latent + 0.25 * e_latent = 1.25 * mean(min dist elems).
__global__ void vq_final(float* __restrict__ out){
    double m = g_loss_acc / (double)QELEMS;
    out[0] = (float)(m + 0.25*m);
}

extern "C" void kernel_launch(void* const* d_in, const int* in_sizes, int n_in,
                              void* d_out, int out_size)
{
    const float* x = (const float*)d_in[0];   // inputs [64,2048,64] fp32
    const float* w = (const float*)d_in[1];   // weight [1024,64] fp32
    float* out = (float*)d_out;

    vq_zero_kernel<<<1,1>>>();
    vq_argmin<<<NROWS/BR, BR>>>(x, w, out);
    vq_gather<<<(QELEMS+255)/256, 256>>>(x, w, out);
    vq_final<<<1,1>>>(out);
}